// round 6
// baseline (speedup 1.0000x reference)
#include <cuda_runtime.h>
#include <cuda_fp16.h>
#include <cstdint>

#define B_ 4
#define L_ 2048
#define D_ 512
#define H_ 8
#define DH_ 64
#define OUT_ELEMS (B_ * L_ * D_)          // 4194304
#define ES 2056                            // e row stride (halves); 4112B %128 = 16 -> ldsm conflict-free

// Scratch (__device__ globals; allocation-free rule)
__device__ __half  g_qh[OUT_ELEMS];
__device__ __half  g_kh[OUT_ELEMS];
__device__ __half  g_vh[OUT_ELEMS];
__device__ float   g_ctx[OUT_ELEMS];
__device__ uint8_t g_mask8[(size_t)B_ * L_ * L_];   // 16.8 MB (fits L2)

// ---------------------------------------------------------------------------
// helpers
// ---------------------------------------------------------------------------
__device__ __forceinline__ uint32_t f2tu(uint32_t x) {
    uint32_t r;
    asm("cvt.rna.tf32.f32 %0, %1;" : "=r"(r) : "f"(__uint_as_float(x)));
    return r;
}
__device__ __forceinline__ void mma_tf32(float4& d, uint32_t a0, uint32_t a1,
                                         uint32_t a2, uint32_t a3,
                                         uint32_t b0, uint32_t b1) {
    asm volatile(
        "mma.sync.aligned.m16n8k8.row.col.f32.tf32.tf32.f32 "
        "{%0,%1,%2,%3}, {%4,%5,%6,%7}, {%8,%9}, {%0,%1,%2,%3};"
        : "+f"(d.x), "+f"(d.y), "+f"(d.z), "+f"(d.w)
        : "r"(a0), "r"(a1), "r"(a2), "r"(a3), "r"(b0), "r"(b1));
}
__device__ __forceinline__ void mma_f16(float4& d, uint32_t a0, uint32_t a1,
                                        uint32_t a2, uint32_t a3,
                                        uint32_t b0, uint32_t b1) {
    asm volatile(
        "mma.sync.aligned.m16n8k16.row.col.f32.f16.f16.f32 "
        "{%0,%1,%2,%3}, {%4,%5,%6,%7}, {%8,%9}, {%0,%1,%2,%3};"
        : "+f"(d.x), "+f"(d.y), "+f"(d.z), "+f"(d.w)
        : "r"(a0), "r"(a1), "r"(a2), "r"(a3), "r"(b0), "r"(b1));
}
__device__ __forceinline__ void ldsm4(uint32_t& r0, uint32_t& r1, uint32_t& r2,
                                      uint32_t& r3, uint32_t addr) {
    asm volatile("ldmatrix.sync.aligned.m8n8.x4.shared.b16 {%0,%1,%2,%3}, [%4];"
                 : "=r"(r0), "=r"(r1), "=r"(r2), "=r"(r3) : "r"(addr));
}
__device__ __forceinline__ void ldsm4t(uint32_t& r0, uint32_t& r1, uint32_t& r2,
                                       uint32_t& r3, uint32_t addr) {
    asm volatile("ldmatrix.sync.aligned.m8n8.x4.trans.shared.b16 {%0,%1,%2,%3}, [%4];"
                 : "=r"(r0), "=r"(r1), "=r"(r2), "=r"(r3) : "r"(addr));
}
__device__ __forceinline__ void cpa16(uint32_t s, const void* g) {
    asm volatile("cp.async.cg.shared.global [%0], [%1], 16;" :: "r"(s), "l"(g));
}
__device__ __forceinline__ void cpcommit() {
    asm volatile("cp.async.commit_group;" ::: "memory");
}
template <int N> __device__ __forceinline__ void cpwait() {
    asm volatile("cp.async.wait_group %0;" :: "n"(N) : "memory");
}

// ---------------------------------------------------------------------------
// mask pack: int32 -> uint8
// ---------------------------------------------------------------------------
__global__ __launch_bounds__(256)
void pack_mask(const int* __restrict__ m) {
    const size_t i = (size_t)blockIdx.x * 256 + threadIdx.x;
    const int4 v = reinterpret_cast<const int4*>(m)[i];
    uchar4 o;
    o.x = v.x ? 1 : 0; o.y = v.y ? 1 : 0; o.z = v.z ? 1 : 0; o.w = v.w ? 1 : 0;
    reinterpret_cast<uchar4*>(g_mask8)[i] = o;
}

// ---------------------------------------------------------------------------
// tf32 GEMM (cp.async double-buffered), templated output (fp32 / fp16).
// ---------------------------------------------------------------------------
__device__ __forceinline__ void gemm_issue(const float* A, const float* W,
                                           int m0, int n0, uint32_t as_s,
                                           uint32_t bs_s, int ki, int buf,
                                           int tid) {
    const float* Ap = A + (size_t)m0 * 512 + ki * 32;
#pragma unroll
    for (int t = 0; t < 4; t++) {
        const int s = tid + 256 * t;
        const int r = s >> 3, c = (s & 7) << 2;
        cpa16(as_s + (uint32_t)((buf * 128 * 36 + r * 36 + c) * 4),
              Ap + (size_t)r * 512 + c);
    }
    const float* Wp = W + (size_t)ki * 32 * 512 + n0;
#pragma unroll
    for (int t = 0; t < 2; t++) {
        const int s = tid + 256 * t;
        const int r = s >> 4, c = (s & 15) << 2;
        cpa16(bs_s + (uint32_t)((buf * 32 * 72 + r * 72 + c) * 4),
              Wp + (size_t)r * 512 + c);
    }
    cpcommit();
}

template <typename OutT>
__global__ __launch_bounds__(256, 2)
void sgemm_ca(const float* __restrict__ A, const float* __restrict__ W,
              const float* __restrict__ bias, OutT* __restrict__ C) {
    extern __shared__ float sm[];
    float* As = sm;                  // [2][128][36]
    float* Bs = sm + 2 * 128 * 36;   // [2][32][72]

    const int tid = threadIdx.x, l = tid & 31, w = tid >> 5;
    const int mg = w >> 1, ng = w & 1;
    const int wm = mg * 32, wn = ng * 32;
    const int lr = l >> 2, lc = l & 3;
    const int m0 = blockIdx.y << 7, n0 = blockIdx.x << 6;

    const uint32_t as_s = (uint32_t)__cvta_generic_to_shared(As);
    const uint32_t bs_s = (uint32_t)__cvta_generic_to_shared(Bs);

    const int g = l >> 3, lo = l & 7;
    const int rA = ((g & 1) << 3) + lo, cA = (g >> 1) << 2;

    float4 acc[2][4];
#pragma unroll
    for (int m = 0; m < 2; m++)
#pragma unroll
        for (int j = 0; j < 4; j++) acc[m][j] = make_float4(0.f, 0.f, 0.f, 0.f);

    gemm_issue(A, W, m0, n0, as_s, bs_s, 0, 0, tid);

    for (int ki = 0; ki < 16; ki++) {
        if (ki + 1 < 16) {
            gemm_issue(A, W, m0, n0, as_s, bs_s, ki + 1, (ki + 1) & 1, tid);
            cpwait<1>();
        } else {
            cpwait<0>();
        }
        __syncthreads();

        const int buf = ki & 1;
        const uint32_t a0b = as_s + (uint32_t)((buf * 128 * 36 + (wm + rA) * 36 + cA) * 4);
        const uint32_t a1b = a0b + 16 * 36 * 4;
        const uint32_t* Bsu = (const uint32_t*)(Bs + buf * 32 * 72);

#pragma unroll
        for (int k8 = 0; k8 < 4; k8++) {
            const int k0 = k8 * 8;
            uint32_t a0[4], a1[4];
            ldsm4(a0[0], a0[1], a0[2], a0[3], a0b + k8 * 32);
            ldsm4(a1[0], a1[1], a1[2], a1[3], a1b + k8 * 32);
#pragma unroll
            for (int i = 0; i < 4; i++) { a0[i] = f2tu(a0[i]); a1[i] = f2tu(a1[i]); }
#pragma unroll
            for (int j = 0; j < 4; j++) {
                const int cb = (k0 + lc) * 72 + wn + 8 * j + lr;
                const uint32_t b0 = f2tu(Bsu[cb]);
                const uint32_t b1 = f2tu(Bsu[cb + 4 * 72]);
                mma_tf32(acc[0][j], a0[0], a0[1], a0[2], a0[3], b0, b1);
                mma_tf32(acc[1][j], a1[0], a1[1], a1[2], a1[3], b0, b1);
            }
        }
        __syncthreads();
    }

#pragma unroll
    for (int m = 0; m < 2; m++)
#pragma unroll
        for (int j = 0; j < 4; j++) {
            const int rg = m0 + wm + 16 * m + lr;
            const int cg = n0 + wn + 8 * j + 2 * lc;
            const float2 bv = *(const float2*)&bias[cg];
            if constexpr (sizeof(OutT) == 2) {
                *(__half2*)&C[(size_t)rg * 512 + cg] =
                    __floats2half2_rn(acc[m][j].x + bv.x, acc[m][j].y + bv.y);
                *(__half2*)&C[(size_t)(rg + 8) * 512 + cg] =
                    __floats2half2_rn(acc[m][j].z + bv.x, acc[m][j].w + bv.y);
            } else {
                *(float2*)&C[(size_t)rg * 512 + cg] =
                    make_float2(acc[m][j].x + bv.x, acc[m][j].y + bv.y);
                *(float2*)&C[(size_t)(rg + 8) * 512 + cg] =
                    make_float2(acc[m][j].z + bv.x, acc[m][j].w + bv.y);
            }
        }
}

// ---------------------------------------------------------------------------
// Fused attention, full-row-e-in-smem. CTA = (bh, 32 q rows).
// Phase 1: loop 16 kv-tiles of 128: QK (fp16 mma) -> masked exp -> e to smem
//          (fp16), rowsum partials in regs. Warp (qg,kg) = 16q x 32kv chunk.
// Reduce rowsums -> inv[32] smem.
// Phase 2: loop 16 kv-tiles: PV from smem-e (warp (qg,dg) = 16q x 16dh) and
//          write NORMALIZED fp32 attn rows straight from smem.
// K and V share one double-buffered smem tile (V streams after K done).
// smem: qs[32][72] + e[32][2056] + kv[2][128][72] (halves) + red[128]+inv[32]
//       = 173,696 B
// ---------------------------------------------------------------------------
__global__ __launch_bounds__(256, 1)
void attn_rowsmem(float* __restrict__ attn) {
    extern __shared__ __half smh[];
    __half* qs = smh;                   // [32][72]
    __half* e  = qs + 32 * 72;          // [32][ES]
    __half* kv = e + 32 * ES;           // [2][128][72]
    float* red = (float*)(kv + 2 * 128 * 72);   // [128]
    float* inv = red + 128;                     // [32]

    const int tid = threadIdx.x, l = tid & 31, w = tid >> 5;
    const int qg = w >> 2;            // 0..1 (16-row q group)
    const int kg = w & 3;             // 0..3 (32-col kv group, phase 1)
    const int dg = w & 3;             // 0..3 (16-col dh group, phase 2)
    const int g = l >> 2, tig = l & 3;
    const int qt = blockIdx.x, bh = blockIdx.y, b = bh >> 3;
    const int q0 = qt * 32;

    const __half* qgm = g_qh + ((size_t)bh * L_ + q0) * DH_;
    const __half* kgm = g_kh + (size_t)bh * L_ * DH_;
    const __half* vgm = g_vh + (size_t)bh * L_ * DH_;
    const uint8_t* mb = g_mask8 + (size_t)b * L_ * L_;

    const uint32_t qs_s = (uint32_t)__cvta_generic_to_shared(qs);
    const uint32_t e_s  = (uint32_t)__cvta_generic_to_shared(e);
    const uint32_t kv_s = (uint32_t)__cvta_generic_to_shared(kv);

#define ISSUE_TILE(src_, kt_, buf_)                                            \
    do {                                                                       \
        _Pragma("unroll")                                                      \
        for (int t = 0; t < 4; t++) {                                          \
            const int s = tid + 256 * t;                                       \
            const int r = s >> 3, c = (s & 7) << 3;                            \
            cpa16(kv_s + (uint32_t)(((buf_) * 128 * 72 + r * 72 + c) * 2),     \
                  (src_) + (size_t)((kt_) * 128 + r) * DH_ + c);               \
        }                                                                      \
        cpcommit();                                                            \
    } while (0)

    // Q (one 16B chunk per thread) + K0 in one group
    {
        const int r = tid >> 3, c = (tid & 7) << 3;
        cpa16(qs_s + (uint32_t)((r * 72 + c) * 2), qgm + (size_t)r * DH_ + c);
    }
    ISSUE_TILE(kgm, 0, 0);

    // ldmatrix lane addressing
    const int a_row = (l & 15), a_col = (l >> 4) << 3;       // A frags
    const int kb_row = ((l >> 4) << 3) + (l & 7);            // B frags (K)
    const int kb_col = ((l >> 3) & 1) << 3;
    const int vb_row = (((l >> 3) & 1) << 3) + (l & 7);      // B trans (V)
    const int vb_col = (l >> 4) << 3;

    cpwait<0>();
    __syncthreads();

    // preload Q A-frags (16 rows x dh64 = 4 k16 chunks)
    uint32_t qa[4][4];
    const uint32_t qaddr = qs_s + (uint32_t)(((16 * qg + a_row) * 72 + a_col) * 2);
#pragma unroll
    for (int kc = 0; kc < 4; kc++)
        ldsm4(qa[kc][0], qa[kc][1], qa[kc][2], qa[kc][3], qaddr + kc * 32);

    float rs0 = 0.f, rs1 = 0.f;
    const int lr0 = 16 * qg + g;          // local q row (and +8)
    const int rg0 = q0 + lr0, rg1 = rg0 + 8;

    // ================= Phase 1: QK -> e(smem), rowsum =================
    for (int kt = 0; kt < 16; kt++) {
        const int buf = kt & 1;
        cpwait<0>();
        __syncthreads();
        if (kt + 1 < 16) ISSUE_TILE(kgm, kt + 1, buf ^ 1);

        float4 acc[4];
#pragma unroll
        for (int j = 0; j < 4; j++) acc[j] = make_float4(0.f, 0.f, 0.f, 0.f);

        const uint32_t ksb = kv_s + (uint32_t)(buf * 128 * 72 * 2);
#pragma unroll
        for (int kc = 0; kc < 4; kc++) {
#pragma unroll
            for (int t = 0; t < 2; t++) {
                const int n0 = 32 * kg + 16 * t;
                uint32_t b0, b1, b2, b3;
                ldsm4(b0, b1, b2, b3,
                      ksb + (uint32_t)(((n0 + kb_row) * 72 + kc * 16 + kb_col) * 2));
                mma_f16(acc[2 * t],     qa[kc][0], qa[kc][1], qa[kc][2], qa[kc][3], b0, b1);
                mma_f16(acc[2 * t + 1], qa[kc][0], qa[kc][1], qa[kc][2], qa[kc][3], b2, b3);
            }
        }

        // masked exp -> e smem (fp16, unnormalized), rowsum partials
        const int cbase = kt * 128 + 32 * kg + 2 * tig;
#pragma unroll
        for (int j = 0; j < 4; j++) {
            const int cg = cbase + 8 * j;
            const uchar2 m0 = *(const uchar2*)(mb + (size_t)rg0 * L_ + cg);
            const uchar2 m1 = *(const uchar2*)(mb + (size_t)rg1 * L_ + cg);
            const float e0 = m0.x ? __expf(acc[j].x * 0.03125f) : 0.f;
            const float e1 = m0.y ? __expf(acc[j].y * 0.03125f) : 0.f;
            const float e2 = m1.x ? __expf(acc[j].z * 0.03125f) : 0.f;
            const float e3 = m1.y ? __expf(acc[j].w * 0.03125f) : 0.f;
            rs0 += e0 + e1;
            rs1 += e2 + e3;
            *(__half2*)&e[lr0 * ES + cg] = __floats2half2_rn(e0, e1);
            *(__half2*)&e[(lr0 + 8) * ES + cg] = __floats2half2_rn(e2, e3);
        }
    }

    // ---- rowsum reduce across lanes then kg-warps ----
    rs0 += __shfl_xor_sync(0xffffffffu, rs0, 1);
    rs0 += __shfl_xor_sync(0xffffffffu, rs0, 2);
    rs1 += __shfl_xor_sync(0xffffffffu, rs1, 1);
    rs1 += __shfl_xor_sync(0xffffffffu, rs1, 2);
    if (tig == 0) {
        red[kg * 32 + lr0] = rs0;
        red[kg * 32 + lr0 + 8] = rs1;
    }
    __syncthreads();

    ISSUE_TILE(vgm, 0, 0);   // V0 prefetch (K buffer fully consumed)

    if (tid < 32) {
        const float s = red[tid] + red[32 + tid] + red[64 + tid] + red[96 + tid];
        inv[tid] = (s > 0.f) ? (1.f / s) : 0.f;
    }
    __syncthreads();

    const float iv0 = inv[lr0], iv1 = inv[lr0 + 8];
    const int wr_r = tid >> 3;                  // attn-write row (0..31)
    const int wr_c = (tid & 7) << 4;            // attn-write col chunk (16 floats)
    const float wr_iv = inv[wr_r];
    float* arow = attn + ((size_t)bh * L_ + q0 + wr_r) * L_;

    float4 ctx[2];
    ctx[0] = make_float4(0.f, 0.f, 0.f, 0.f);
    ctx[1] = make_float4(0.f, 0.f, 0.f, 0.f);
    const uint32_t ea = e_s + (uint32_t)(((16 * qg + a_row) * ES + a_col) * 2);

    // ================= Phase 2: PV + normalized attn writes =================
    for (int kt = 0; kt < 16; kt++) {
        const int buf = kt & 1;
        cpwait<0>();
        __syncthreads();
        if (kt + 1 < 16) ISSUE_TILE(vgm, kt + 1, buf ^ 1);

        const uint32_t vsb = kv_s + (uint32_t)(buf * 128 * 72 * 2);
#pragma unroll
        for (int kc = 0; kc < 8; kc++) {
            uint32_t a0, a1, a2, a3, b0, b1, b2, b3;
            ldsm4(a0, a1, a2, a3, ea + (uint32_t)((kt * 128 + kc * 16) * 2));
            ldsm4t(b0, b1, b2, b3,
                   vsb + (uint32_t)(((kc * 16 + vb_row) * 72 + 16 * dg + vb_col) * 2));
            mma_f16(ctx[0], a0, a1, a2, a3, b0, b1);
            mma_f16(ctx[1], a0, a1, a2, a3, b2, b3);
        }

        // normalized fp32 attn write for this tile (independent of V)
        {
            const __half2* ep = (const __half2*)&e[wr_r * ES + kt * 128 + wr_c];
            float4 o[4];
#pragma unroll
            for (int q = 0; q < 4; q++) {
                const float2 f0 = __half22float2(ep[2 * q]);
                const float2 f1 = __half22float2(ep[2 * q + 1]);
                o[q] = make_float4(f0.x * wr_iv, f0.y * wr_iv,
                                   f1.x * wr_iv, f1.y * wr_iv);
            }
            float4* dst = (float4*)(arow + kt * 128 + wr_c);
#pragma unroll
            for (int q = 0; q < 4; q++) dst[q] = o[q];
        }
    }

    // ---- ctx write (normalized fp32) ----
#pragma unroll
    for (int j = 0; j < 2; j++) {
        const int cd = 16 * dg + 8 * j + 2 * tig;
        *(float2*)&g_ctx[((size_t)bh * L_ + rg0) * DH_ + cd] =
            make_float2(ctx[j].x * iv0, ctx[j].y * iv0);
        *(float2*)&g_ctx[((size_t)bh * L_ + rg1) * DH_ + cd] =
            make_float2(ctx[j].z * iv1, ctx[j].w * iv1);
    }
#undef ISSUE_TILE
}

// ---------------------------------------------------------------------------
extern "C" void kernel_launch(void* const* d_in, const int* in_sizes, int n_in,
                              void* d_out, int out_size) {
    const float* Q  = (const float*)d_in[0];
    const float* K  = (const float*)d_in[1];
    const float* V  = (const float*)d_in[2];
    const int*   Mk = (const int*)d_in[3];
    const float* Wq = (const float*)d_in[4];
    const float* bq = (const float*)d_in[5];
    const float* Wk = (const float*)d_in[6];
    const float* bk = (const float*)d_in[7];
    const float* Wv = (const float*)d_in[8];
    const float* bv = (const float*)d_in[9];
    const float* Wo = (const float*)d_in[10];
    const float* bo = (const float*)d_in[11];

    __half *qh, *kh, *vh;
    float *ctx;
    cudaGetSymbolAddress((void**)&qh, g_qh);
    cudaGetSymbolAddress((void**)&kh, g_kh);
    cudaGetSymbolAddress((void**)&vh, g_vh);
    cudaGetSymbolAddress((void**)&ctx, g_ctx);

    float* out  = (float*)d_out;
    float* attn = out + OUT_ELEMS;   // concat(out, attn_dist)

    const int smem_gemm = (2 * 128 * 36 + 2 * 32 * 72) * 4;                 // 55296
    const int smem_attn = (32 * 72 + 32 * ES + 2 * 128 * 72) * 2 + 160 * 4; // 173696
    cudaFuncSetAttribute(sgemm_ca<__half>, cudaFuncAttributeMaxDynamicSharedMemorySize, smem_gemm);
    cudaFuncSetAttribute(sgemm_ca<float>, cudaFuncAttributeMaxDynamicSharedMemorySize, smem_gemm);
    cudaFuncSetAttribute(attn_rowsmem, cudaFuncAttributeMaxDynamicSharedMemorySize, smem_attn);

    pack_mask<<<(B_ * L_ * L_) / 4 / 256, 256>>>(Mk);

    const dim3 gg(8, 64);    // N/64, M/128
    sgemm_ca<__half><<<gg, 256, smem_gemm>>>(Q, Wq, bq, qh);
    sgemm_ca<__half><<<gg, 256, smem_gemm>>>(K, Wk, bk, kh);
    sgemm_ca<__half><<<gg, 256, smem_gemm>>>(V, Wv, bv, vh);

    const dim3 ga(64, 32);   // q-tiles of 32, b*h
    attn_rowsmem<<<ga, 256, smem_attn>>>(attn);

    sgemm_ca<float><<<gg, 256, smem_gemm>>>(ctx, Wo, bo, out);
}

// round 7
// speedup vs baseline: 1.2788x; 1.2788x over previous
#include <cuda_runtime.h>
#include <cuda_fp16.h>
#include <cstdint>

#define B_ 4
#define L_ 2048
#define D_ 512
#define H_ 8
#define DH_ 64
#define OUT_ELEMS (B_ * L_ * D_)          // 4194304

// Scratch (__device__ globals; allocation-free rule)
__device__ __half  g_qin[OUT_ELEMS];                // fp16 inputs
__device__ __half  g_kin[OUT_ELEMS];
__device__ __half  g_vin[OUT_ELEMS];
__device__ __half  g_wq[D_ * D_], g_wk[D_ * D_], g_wv[D_ * D_], g_wo[D_ * D_];
__device__ __half  g_qh[OUT_ELEMS];                 // fp16 projections
__device__ __half  g_kh[OUT_ELEMS];
__device__ __half  g_vh[OUT_ELEMS];
__device__ __half  g_ctxh[OUT_ELEMS];               // fp16 attention context
__device__ float   g_inv[B_ * H_ * L_];
__device__ uint8_t g_mask8[(size_t)B_ * L_ * L_];   // 16.8 MB (fits L2)
__device__ __half  g_eh[(size_t)B_ * H_ * L_ * L_]; // 268 MB unnormalized e

// ---------------------------------------------------------------------------
// helpers
// ---------------------------------------------------------------------------
__device__ __forceinline__ void mma_f16(float4& d, uint32_t a0, uint32_t a1,
                                        uint32_t a2, uint32_t a3,
                                        uint32_t b0, uint32_t b1) {
    asm volatile(
        "mma.sync.aligned.m16n8k16.row.col.f32.f16.f16.f32 "
        "{%0,%1,%2,%3}, {%4,%5,%6,%7}, {%8,%9}, {%0,%1,%2,%3};"
        : "+f"(d.x), "+f"(d.y), "+f"(d.z), "+f"(d.w)
        : "r"(a0), "r"(a1), "r"(a2), "r"(a3), "r"(b0), "r"(b1));
}
__device__ __forceinline__ void ldsm4(uint32_t& r0, uint32_t& r1, uint32_t& r2,
                                      uint32_t& r3, uint32_t addr) {
    asm volatile("ldmatrix.sync.aligned.m8n8.x4.shared.b16 {%0,%1,%2,%3}, [%4];"
                 : "=r"(r0), "=r"(r1), "=r"(r2), "=r"(r3) : "r"(addr));
}
__device__ __forceinline__ void ldsm4t(uint32_t& r0, uint32_t& r1, uint32_t& r2,
                                       uint32_t& r3, uint32_t addr) {
    asm volatile("ldmatrix.sync.aligned.m8n8.x4.trans.shared.b16 {%0,%1,%2,%3}, [%4];"
                 : "=r"(r0), "=r"(r1), "=r"(r2), "=r"(r3) : "r"(addr));
}
__device__ __forceinline__ void cpa16(uint32_t s, const void* g) {
    asm volatile("cp.async.cg.shared.global [%0], [%1], 16;" :: "r"(s), "l"(g));
}
__device__ __forceinline__ void cpcommit() {
    asm volatile("cp.async.commit_group;" ::: "memory");
}
template <int N> __device__ __forceinline__ void cpwait() {
    asm volatile("cp.async.wait_group %0;" :: "n"(N) : "memory");
}

// ---------------------------------------------------------------------------
// mask pack: int32 -> uint8
// ---------------------------------------------------------------------------
__global__ __launch_bounds__(256)
void pack_mask(const int* __restrict__ m) {
    const size_t i = (size_t)blockIdx.x * 256 + threadIdx.x;
    const int4 v = reinterpret_cast<const int4*>(m)[i];
    uchar4 o;
    o.x = v.x ? 1 : 0; o.y = v.y ? 1 : 0; o.z = v.z ? 1 : 0; o.w = v.w ? 1 : 0;
    reinterpret_cast<uchar4*>(g_mask8)[i] = o;
}

// ---------------------------------------------------------------------------
// fp32 -> fp16 convert (vectorized, n multiple of 1024)
// ---------------------------------------------------------------------------
__global__ __launch_bounds__(256)
void f2h(const float* __restrict__ s, __half* __restrict__ d) {
    const size_t i = (size_t)blockIdx.x * 256 + threadIdx.x;
    const float4 v = reinterpret_cast<const float4*>(s)[i];
    __half2 h0 = __floats2half2_rn(v.x, v.y);
    __half2 h1 = __floats2half2_rn(v.z, v.w);
    uint2 o;
    o.x = *(uint32_t*)&h0;
    o.y = *(uint32_t*)&h1;
    reinterpret_cast<uint2*>(d)[i] = o;
}

// ---------------------------------------------------------------------------
// fp16 GEMM: C[M,512] = A[M,512] @ W[512,512] + bias (fp32 accum/bias).
// Block 128x64, 8 warps (4m x 2n), warp 32x32, k-stage 64, cp.async 2-stage.
// smem halves: Ah[2][128][72] + Wh[2][64][72] = 55296 B
// ---------------------------------------------------------------------------
__device__ __forceinline__ void hgemm_issue(const __half* A, const __half* W,
                                            int m0, int n0, uint32_t as_s,
                                            uint32_t bs_s, int ki, int buf,
                                            int tid) {
    const __half* Ap = A + (size_t)m0 * 512 + ki * 64;
#pragma unroll
    for (int t = 0; t < 4; t++) {
        const int s = tid + 256 * t;            // 1024 chunks (128 x 8)
        const int r = s >> 3, c = (s & 7) << 3;
        cpa16(as_s + (uint32_t)((buf * 128 * 72 + r * 72 + c) * 2),
              Ap + (size_t)r * 512 + c);
    }
    const __half* Wp = W + (size_t)ki * 64 * 512 + n0;
#pragma unroll
    for (int t = 0; t < 2; t++) {
        const int s = tid + 256 * t;            // 512 chunks (64 x 8)
        const int r = s >> 3, c = (s & 7) << 3;
        cpa16(bs_s + (uint32_t)((buf * 64 * 72 + r * 72 + c) * 2),
              Wp + (size_t)r * 512 + c);
    }
    cpcommit();
}

template <typename OutT>
__global__ __launch_bounds__(256, 2)
void hgemm(const __half* __restrict__ A, const __half* __restrict__ W,
           const float* __restrict__ bias, OutT* __restrict__ C) {
    extern __shared__ __half smh[];
    __half* Ah = smh;                  // [2][128][72]
    __half* Wh = smh + 2 * 128 * 72;   // [2][64][72]

    const int tid = threadIdx.x, l = tid & 31, w = tid >> 5;
    const int mg = w >> 1, ng = w & 1;
    const int wm = mg * 32, wn = ng * 32;
    const int lr = l >> 2, lc = l & 3;
    const int m0 = blockIdx.y << 7, n0 = blockIdx.x << 6;

    const uint32_t as_s = (uint32_t)__cvta_generic_to_shared(Ah);
    const uint32_t bs_s = (uint32_t)__cvta_generic_to_shared(Wh);

    // ldmatrix lane addressing
    const int a_row = (l & 15), a_col = (l >> 4) << 3;       // A frags
    const int vb_row = (((l >> 3) & 1) << 3) + (l & 7);      // B trans frags
    const int vb_col = (l >> 4) << 3;

    float4 acc[2][4];
#pragma unroll
    for (int m = 0; m < 2; m++)
#pragma unroll
        for (int j = 0; j < 4; j++) acc[m][j] = make_float4(0.f, 0.f, 0.f, 0.f);

    hgemm_issue(A, W, m0, n0, as_s, bs_s, 0, 0, tid);

    for (int ki = 0; ki < 8; ki++) {
        if (ki + 1 < 8) {
            hgemm_issue(A, W, m0, n0, as_s, bs_s, ki + 1, (ki + 1) & 1, tid);
            cpwait<1>();
        } else {
            cpwait<0>();
        }
        __syncthreads();

        const int buf = ki & 1;
        const uint32_t a0b = as_s + (uint32_t)((buf * 128 * 72 + (wm + a_row) * 72 + a_col) * 2);
        const uint32_t a1b = a0b + 16 * 72 * 2;
        const uint32_t wb = bs_s + (uint32_t)((buf * 64 * 72) * 2);

#pragma unroll
        for (int kc = 0; kc < 4; kc++) {
            uint32_t a0[4], a1[4];
            ldsm4(a0[0], a0[1], a0[2], a0[3], a0b + kc * 32);
            ldsm4(a1[0], a1[1], a1[2], a1[3], a1b + kc * 32);
#pragma unroll
            for (int j = 0; j < 2; j++) {
                uint32_t b0, b1, b2, b3;
                ldsm4t(b0, b1, b2, b3,
                       wb + (uint32_t)(((kc * 16 + vb_row) * 72 + wn + 16 * j + vb_col) * 2));
                mma_f16(acc[0][2 * j],     a0[0], a0[1], a0[2], a0[3], b0, b1);
                mma_f16(acc[1][2 * j],     a1[0], a1[1], a1[2], a1[3], b0, b1);
                mma_f16(acc[0][2 * j + 1], a0[0], a0[1], a0[2], a0[3], b2, b3);
                mma_f16(acc[1][2 * j + 1], a1[0], a1[1], a1[2], a1[3], b2, b3);
            }
        }
        __syncthreads();
    }

#pragma unroll
    for (int m = 0; m < 2; m++)
#pragma unroll
        for (int j = 0; j < 4; j++) {
            const int rg = m0 + wm + 16 * m + lr;
            const int cg = n0 + wn + 8 * j + 2 * lc;
            const float2 bv = *(const float2*)&bias[cg];
            if constexpr (sizeof(OutT) == 2) {
                *(__half2*)&C[(size_t)rg * 512 + cg] =
                    __floats2half2_rn(acc[m][j].x + bv.x, acc[m][j].y + bv.y);
                *(__half2*)&C[(size_t)(rg + 8) * 512 + cg] =
                    __floats2half2_rn(acc[m][j].z + bv.x, acc[m][j].w + bv.y);
            } else {
                *(float2*)&C[(size_t)rg * 512 + cg] =
                    make_float2(acc[m][j].x + bv.x, acc[m][j].y + bv.y);
                *(float2*)&C[(size_t)(rg + 8) * 512 + cg] =
                    make_float2(acc[m][j].z + bv.x, acc[m][j].w + bv.y);
            }
        }
}

// ---------------------------------------------------------------------------
// fp16 fused attention (R5 structure). CTA = (bh, 128 q rows); warp owns
// 16 q-rows x full 64 kv cols. QK -> masked exp -> fp16 e to g_eh + register
// repack -> PV from registers. ctx (fp16) scaled by 1/rowsum.
// smem halves: qs[128][72] + ks[2][64][72] + vs[2][64][72] (+ red 128 f32)
// ---------------------------------------------------------------------------
__global__ __launch_bounds__(256, 2)
void attn_fp16(float* __restrict__ dummy) {
    extern __shared__ __half smh[];
    __half* qs = smh;                  // [128][72]
    __half* ks = qs + 128 * 72;        // [2][64][72]
    __half* vs = ks + 2 * 64 * 72;     // [2][64][72]
    float* red = (float*)(vs + 2 * 64 * 72);   // [128]

    const int tid = threadIdx.x, l = tid & 31, w = tid >> 5;
    const int wq = w * 16;
    const int g = l >> 2, tig = l & 3;
    const int qt = blockIdx.x, bh = blockIdx.y, b = bh >> 3;
    const int q0 = qt * 128;

    const __half* qg = g_qh + ((size_t)bh * L_ + q0) * DH_;
    const __half* kg = g_kh + (size_t)bh * L_ * DH_;
    const __half* vg = g_vh + (size_t)bh * L_ * DH_;
    const uint8_t* mb = g_mask8 + (size_t)b * L_ * L_;

    const uint32_t qs_s = (uint32_t)__cvta_generic_to_shared(qs);
    const uint32_t ks_s = (uint32_t)__cvta_generic_to_shared(ks);
    const uint32_t vs_s = (uint32_t)__cvta_generic_to_shared(vs);

#define ISSUE_K(kt_, buf_)                                                     \
    do {                                                                       \
        _Pragma("unroll")                                                      \
        for (int t = 0; t < 2; t++) {                                          \
            const int s = tid + 256 * t;                                       \
            const int r = s >> 3, c = (s & 7) << 3;                            \
            cpa16(ks_s + (uint32_t)(((buf_) * 64 * 72 + r * 72 + c) * 2),      \
                  kg + (size_t)((kt_) * 64 + r) * DH_ + c);                    \
        }                                                                      \
        cpcommit();                                                            \
    } while (0)
#define ISSUE_V(kt_, buf_)                                                     \
    do {                                                                       \
        _Pragma("unroll")                                                      \
        for (int t = 0; t < 2; t++) {                                          \
            const int s = tid + 256 * t;                                       \
            const int r = s >> 3, c = (s & 7) << 3;                            \
            cpa16(vs_s + (uint32_t)(((buf_) * 64 * 72 + r * 72 + c) * 2),      \
                  vg + (size_t)((kt_) * 64 + r) * DH_ + c);                    \
        }                                                                      \
        cpcommit();                                                            \
    } while (0)

    // Q (group), K0 (group), V0 (group)
#pragma unroll
    for (int t = 0; t < 4; t++) {
        const int s = tid + 256 * t;
        const int r = s >> 3, c = (s & 7) << 3;
        cpa16(qs_s + (uint32_t)((r * 72 + c) * 2), qg + (size_t)r * DH_ + c);
    }
    cpcommit();
    ISSUE_K(0, 0);
    ISSUE_V(0, 0);

    // ldmatrix lane addressing
    const int a_row = wq + (l & 15);
    const int a_col = (l >> 4) << 3;
    const int kb_row = ((l >> 4) << 3) + (l & 7);
    const int kb_col = ((l >> 3) & 1) << 3;
    const int vb_row = (((l >> 3) & 1) << 3) + (l & 7);
    const int vb_col = (l >> 4) << 3;

    cpwait<2>();
    __syncthreads();

    uint32_t qa[4][4];
    const uint32_t qaddr = qs_s + (uint32_t)((a_row * 72 + a_col) * 2);
#pragma unroll
    for (int kc = 0; kc < 4; kc++)
        ldsm4(qa[kc][0], qa[kc][1], qa[kc][2], qa[kc][3], qaddr + kc * 32);

    float4 ctx[8];
#pragma unroll
    for (int j = 0; j < 8; j++) ctx[j] = make_float4(0.f, 0.f, 0.f, 0.f);
    float rs0 = 0.f, rs1 = 0.f;

    const int rg0 = q0 + wq + g;
    const int rg1 = rg0 + 8;
    __half* ebase0 = g_eh + ((size_t)bh * L_ + rg0) * L_;
    __half* ebase1 = g_eh + ((size_t)bh * L_ + rg1) * L_;

    for (int kt = 0; kt < 32; kt++) {
        const int buf = kt & 1;
        cpwait<1>();
        __syncthreads();

        // ---- QK^T ----
        float4 acc[8];
#pragma unroll
        for (int j = 0; j < 8; j++) acc[j] = make_float4(0.f, 0.f, 0.f, 0.f);

        const uint32_t ksb = ks_s + (uint32_t)(buf * 64 * 72 * 2);
#pragma unroll
        for (int kc = 0; kc < 4; kc++) {
#pragma unroll
            for (int q4 = 0; q4 < 4; q4++) {
                uint32_t b0, b1, b2, b3;
                ldsm4(b0, b1, b2, b3,
                      ksb + (uint32_t)(((q4 * 16 + kb_row) * 72 + kc * 16 + kb_col) * 2));
                mma_f16(acc[2 * q4],     qa[kc][0], qa[kc][1], qa[kc][2], qa[kc][3], b0, b1);
                mma_f16(acc[2 * q4 + 1], qa[kc][0], qa[kc][1], qa[kc][2], qa[kc][3], b2, b3);
            }
        }

        if (kt + 1 < 32) ISSUE_K(kt + 1, buf ^ 1);

        // ---- epilogue: masked exp, fp16 store, half2 repack ----
        uint32_t plo[8], phi[8];
        const uint8_t* m0p = mb + (size_t)rg0 * L_ + kt * 64 + 2 * tig;
        const uint8_t* m1p = mb + (size_t)rg1 * L_ + kt * 64 + 2 * tig;
#pragma unroll
        for (int j = 0; j < 8; j++) {
            const int co = 8 * j;
            const uchar2 m0 = *(const uchar2*)(m0p + co);
            const uchar2 m1 = *(const uchar2*)(m1p + co);
            const float e0 = m0.x ? __expf(acc[j].x * 0.03125f) : 0.f;
            const float e1 = m0.y ? __expf(acc[j].y * 0.03125f) : 0.f;
            const float e2 = m1.x ? __expf(acc[j].z * 0.03125f) : 0.f;
            const float e3 = m1.y ? __expf(acc[j].w * 0.03125f) : 0.f;
            rs0 += e0 + e1;
            rs1 += e2 + e3;
            const __half2 h0 = __floats2half2_rn(e0, e1);
            const __half2 h1 = __floats2half2_rn(e2, e3);
            plo[j] = *(const uint32_t*)&h0;
            phi[j] = *(const uint32_t*)&h1;
            const int cg = kt * 64 + co + 2 * tig;
            *(__half2*)(ebase0 + cg) = h0;
            *(__half2*)(ebase1 + cg) = h1;
        }

        if (kt + 1 < 32) cpwait<1>(); else cpwait<0>();
        __syncthreads();

        // ---- P @ V (A from registers) ----
        const uint32_t vsb = vs_s + (uint32_t)(buf * 64 * 72 * 2);
#pragma unroll
        for (int kc = 0; kc < 4; kc++) {
            const uint32_t a0 = plo[2 * kc], a1 = phi[2 * kc];
            const uint32_t a2 = plo[2 * kc + 1], a3 = phi[2 * kc + 1];
#pragma unroll
            for (int q4 = 0; q4 < 4; q4++) {
                uint32_t b0, b1, b2, b3;
                ldsm4t(b0, b1, b2, b3,
                       vsb + (uint32_t)(((kc * 16 + vb_row) * 72 + q4 * 16 + vb_col) * 2));
                mma_f16(ctx[2 * q4],     a0, a1, a2, a3, b0, b1);
                mma_f16(ctx[2 * q4 + 1], a0, a1, a2, a3, b2, b3);
            }
        }

        if (kt + 1 < 32) ISSUE_V(kt + 1, buf ^ 1);
    }

    // ---- rowsum reduce -> inv ----
    rs0 += __shfl_xor_sync(0xffffffffu, rs0, 1);
    rs0 += __shfl_xor_sync(0xffffffffu, rs0, 2);
    rs1 += __shfl_xor_sync(0xffffffffu, rs1, 1);
    rs1 += __shfl_xor_sync(0xffffffffu, rs1, 2);
    if (tig == 0) {
        red[wq + g] = rs0;
        red[wq + 8 + g] = rs1;
    }
    __syncthreads();
    if (tid < 128) {
        const float s = red[tid];
        const float iv = (s > 0.f) ? (1.f / s) : 0.f;
        g_inv[(size_t)bh * L_ + q0 + tid] = iv;
        red[tid] = iv;
    }
    __syncthreads();
    const float iv0 = red[wq + g];
    const float iv1 = red[wq + 8 + g];

    // ---- ctx write (normalized fp16) ----
#pragma unroll
    for (int j = 0; j < 8; j++) {
        const int cd = 8 * j + 2 * tig;
        *(__half2*)&g_ctxh[((size_t)bh * L_ + rg0) * DH_ + cd] =
            __floats2half2_rn(ctx[j].x * iv0, ctx[j].y * iv0);
        *(__half2*)&g_ctxh[((size_t)bh * L_ + rg1) * DH_ + cd] =
            __floats2half2_rn(ctx[j].z * iv1, ctx[j].w * iv1);
    }
    (void)dummy;
#undef ISSUE_K
#undef ISSUE_V
}

// ---------------------------------------------------------------------------
// rescale: attn[row][:] = fp32(g_eh[row][:]) * g_inv[row]
// ---------------------------------------------------------------------------
__global__ __launch_bounds__(256)
void rescale_attn(float* __restrict__ attn) {
    const int row = blockIdx.x;
    const float iv = g_inv[row];
    const uint4 u = reinterpret_cast<const uint4*>(g_eh + (size_t)row * L_)[threadIdx.x];
    float4 o0, o1;
    {
        const float2 f0 = __half22float2(*(const __half2*)&u.x);
        const float2 f1 = __half22float2(*(const __half2*)&u.y);
        o0 = make_float4(f0.x * iv, f0.y * iv, f1.x * iv, f1.y * iv);
    }
    {
        const float2 f0 = __half22float2(*(const __half2*)&u.z);
        const float2 f1 = __half22float2(*(const __half2*)&u.w);
        o1 = make_float4(f0.x * iv, f0.y * iv, f1.x * iv, f1.y * iv);
    }
    float4* dst = reinterpret_cast<float4*>(attn + (size_t)row * L_);
    dst[2 * threadIdx.x] = o0;
    dst[2 * threadIdx.x + 1] = o1;
}

// ---------------------------------------------------------------------------
extern "C" void kernel_launch(void* const* d_in, const int* in_sizes, int n_in,
                              void* d_out, int out_size) {
    const float* Q  = (const float*)d_in[0];
    const float* K  = (const float*)d_in[1];
    const float* V  = (const float*)d_in[2];
    const int*   Mk = (const int*)d_in[3];
    const float* Wq = (const float*)d_in[4];
    const float* bq = (const float*)d_in[5];
    const float* Wk = (const float*)d_in[6];
    const float* bk = (const float*)d_in[7];
    const float* Wv = (const float*)d_in[8];
    const float* bv = (const float*)d_in[9];
    const float* Wo = (const float*)d_in[10];
    const float* bo = (const float*)d_in[11];

    __half *qin, *kin, *vin, *wq, *wk, *wv, *wo, *qh, *kh, *vh, *ctxh;
    cudaGetSymbolAddress((void**)&qin, g_qin);
    cudaGetSymbolAddress((void**)&kin, g_kin);
    cudaGetSymbolAddress((void**)&vin, g_vin);
    cudaGetSymbolAddress((void**)&wq, g_wq);
    cudaGetSymbolAddress((void**)&wk, g_wk);
    cudaGetSymbolAddress((void**)&wv, g_wv);
    cudaGetSymbolAddress((void**)&wo, g_wo);
    cudaGetSymbolAddress((void**)&qh, g_qh);
    cudaGetSymbolAddress((void**)&kh, g_kh);
    cudaGetSymbolAddress((void**)&vh, g_vh);
    cudaGetSymbolAddress((void**)&ctxh, g_ctxh);

    float* out  = (float*)d_out;
    float* attn = out + OUT_ELEMS;   // concat(out, attn_dist)

    const int smem_gemm = (2 * 128 * 72 + 2 * 64 * 72) * 2;         // 55296
    const int smem_attn = (128 * 72 + 4 * 64 * 72) * 2 + 128 * 4;   // 55808
    cudaFuncSetAttribute(hgemm<__half>, cudaFuncAttributeMaxDynamicSharedMemorySize, smem_gemm);
    cudaFuncSetAttribute(hgemm<float>, cudaFuncAttributeMaxDynamicSharedMemorySize, smem_gemm);
    cudaFuncSetAttribute(attn_fp16, cudaFuncAttributeMaxDynamicSharedMemorySize, smem_attn);

    pack_mask<<<(B_ * L_ * L_) / 4 / 256, 256>>>(Mk);

    // fp32 -> fp16 converts (inputs + weights)
    f2h<<<OUT_ELEMS / 4 / 256, 256>>>(Q, qin);
    f2h<<<OUT_ELEMS / 4 / 256, 256>>>(K, kin);
    f2h<<<OUT_ELEMS / 4 / 256, 256>>>(V, vin);
    f2h<<<(D_ * D_) / 4 / 256, 256>>>(Wq, wq);
    f2h<<<(D_ * D_) / 4 / 256, 256>>>(Wk, wk);
    f2h<<<(D_ * D_) / 4 / 256, 256>>>(Wv, wv);
    f2h<<<(D_ * D_) / 4 / 256, 256>>>(Wo, wo);

    const dim3 gg(8, 64);    // N/64, M/128
    hgemm<__half><<<gg, 256, smem_gemm>>>(qin, wq, bq, qh);
    hgemm<__half><<<gg, 256, smem_gemm>>>(kin, wk, bk, kh);
    hgemm<__half><<<gg, 256, smem_gemm>>>(vin, wv, bv, vh);

    const dim3 ga(16, 32);   // q-tiles of 128, b*h
    attn_fp16<<<ga, 256, smem_attn>>>(attn);

    rescale_attn<<<B_ * H_ * L_, 256>>>(attn);

    hgemm<float><<<gg, 256, smem_gemm>>>(ctxh, wo, bo, out);
}

// round 8
// speedup vs baseline: 1.4143x; 1.1060x over previous
#include <cuda_runtime.h>
#include <cuda_fp16.h>
#include <cstdint>

#define B_ 4
#define L_ 2048
#define D_ 512
#define H_ 8
#define DH_ 64
#define OUT_ELEMS (B_ * L_ * D_)          // 4194304
#define LOG2E_DIV32 0.04507129744f         // log2(e)/32

// Scratch (__device__ globals; allocation-free rule)
__device__ __half  g_qin[OUT_ELEMS];                // fp16 inputs
__device__ __half  g_kin[OUT_ELEMS];
__device__ __half  g_vin[OUT_ELEMS];
__device__ __half  g_wq[D_ * D_], g_wk[D_ * D_], g_wv[D_ * D_], g_wo[D_ * D_];
__device__ __half  g_qh[OUT_ELEMS];                 // fp16 projections
__device__ __half  g_kh[OUT_ELEMS];
__device__ __half  g_vh[OUT_ELEMS];
__device__ __half  g_ctxh[OUT_ELEMS];               // fp16 attention context
__device__ float   g_inv[B_ * H_ * L_];
__device__ uint8_t g_mask8[(size_t)B_ * L_ * L_];   // 16.8 MB (fits L2)
__device__ __half  g_eh[(size_t)B_ * H_ * L_ * L_]; // 268 MB unnormalized e

// ---------------------------------------------------------------------------
// helpers
// ---------------------------------------------------------------------------
__device__ __forceinline__ void mma_f16(float4& d, uint32_t a0, uint32_t a1,
                                        uint32_t a2, uint32_t a3,
                                        uint32_t b0, uint32_t b1) {
    asm volatile(
        "mma.sync.aligned.m16n8k16.row.col.f32.f16.f16.f32 "
        "{%0,%1,%2,%3}, {%4,%5,%6,%7}, {%8,%9}, {%0,%1,%2,%3};"
        : "+f"(d.x), "+f"(d.y), "+f"(d.z), "+f"(d.w)
        : "r"(a0), "r"(a1), "r"(a2), "r"(a3), "r"(b0), "r"(b1));
}
__device__ __forceinline__ void ldsm4(uint32_t& r0, uint32_t& r1, uint32_t& r2,
                                      uint32_t& r3, uint32_t addr) {
    asm volatile("ldmatrix.sync.aligned.m8n8.x4.shared.b16 {%0,%1,%2,%3}, [%4];"
                 : "=r"(r0), "=r"(r1), "=r"(r2), "=r"(r3) : "r"(addr));
}
__device__ __forceinline__ void ldsm4t(uint32_t& r0, uint32_t& r1, uint32_t& r2,
                                       uint32_t& r3, uint32_t addr) {
    asm volatile("ldmatrix.sync.aligned.m8n8.x4.trans.shared.b16 {%0,%1,%2,%3}, [%4];"
                 : "=r"(r0), "=r"(r1), "=r"(r2), "=r"(r3) : "r"(addr));
}
__device__ __forceinline__ void cpa16(uint32_t s, const void* g) {
    asm volatile("cp.async.cg.shared.global [%0], [%1], 16;" :: "r"(s), "l"(g));
}
__device__ __forceinline__ void cpcommit() {
    asm volatile("cp.async.commit_group;" ::: "memory");
}
template <int N> __device__ __forceinline__ void cpwait() {
    asm volatile("cp.async.wait_group %0;" :: "n"(N) : "memory");
}

// ---------------------------------------------------------------------------
// mask pack: int32 -> uint8
// ---------------------------------------------------------------------------
__global__ __launch_bounds__(256)
void pack_mask(const int* __restrict__ m) {
    const size_t i = (size_t)blockIdx.x * 256 + threadIdx.x;
    const int4 v = reinterpret_cast<const int4*>(m)[i];
    uchar4 o;
    o.x = v.x ? 1 : 0; o.y = v.y ? 1 : 0; o.z = v.z ? 1 : 0; o.w = v.w ? 1 : 0;
    reinterpret_cast<uchar4*>(g_mask8)[i] = o;
}

// ---------------------------------------------------------------------------
// fp32 -> fp16 convert (vectorized)
// ---------------------------------------------------------------------------
__global__ __launch_bounds__(256)
void f2h(const float* __restrict__ s, __half* __restrict__ d) {
    const size_t i = (size_t)blockIdx.x * 256 + threadIdx.x;
    const float4 v = reinterpret_cast<const float4*>(s)[i];
    __half2 h0 = __floats2half2_rn(v.x, v.y);
    __half2 h1 = __floats2half2_rn(v.z, v.w);
    uint2 o;
    o.x = *(uint32_t*)&h0;
    o.y = *(uint32_t*)&h1;
    reinterpret_cast<uint2*>(d)[i] = o;
}

// ---------------------------------------------------------------------------
// fp16 GEMM: C[M,512] = A[M,512] @ W[512,512] + bias (fp32 accum/bias).
// Block 128x64, 8 warps (4m x 2n), warp 32x32, k-stage 64, cp.async 2-stage.
// ---------------------------------------------------------------------------
__device__ __forceinline__ void hgemm_issue(const __half* A, const __half* W,
                                            int m0, int n0, uint32_t as_s,
                                            uint32_t bs_s, int ki, int buf,
                                            int tid) {
    const __half* Ap = A + (size_t)m0 * 512 + ki * 64;
#pragma unroll
    for (int t = 0; t < 4; t++) {
        const int s = tid + 256 * t;
        const int r = s >> 3, c = (s & 7) << 3;
        cpa16(as_s + (uint32_t)((buf * 128 * 72 + r * 72 + c) * 2),
              Ap + (size_t)r * 512 + c);
    }
    const __half* Wp = W + (size_t)ki * 64 * 512 + n0;
#pragma unroll
    for (int t = 0; t < 2; t++) {
        const int s = tid + 256 * t;
        const int r = s >> 3, c = (s & 7) << 3;
        cpa16(bs_s + (uint32_t)((buf * 64 * 72 + r * 72 + c) * 2),
              Wp + (size_t)r * 512 + c);
    }
    cpcommit();
}

template <typename OutT>
__global__ __launch_bounds__(256, 2)
void hgemm(const __half* __restrict__ A, const __half* __restrict__ W,
           const float* __restrict__ bias, OutT* __restrict__ C) {
    extern __shared__ __half smh[];
    __half* Ah = smh;                  // [2][128][72]
    __half* Wh = smh + 2 * 128 * 72;   // [2][64][72]

    const int tid = threadIdx.x, l = tid & 31, w = tid >> 5;
    const int mg = w >> 1, ng = w & 1;
    const int wm = mg * 32, wn = ng * 32;
    const int lr = l >> 2, lc = l & 3;
    const int m0 = blockIdx.y << 7, n0 = blockIdx.x << 6;

    const uint32_t as_s = (uint32_t)__cvta_generic_to_shared(Ah);
    const uint32_t bs_s = (uint32_t)__cvta_generic_to_shared(Wh);

    const int a_row = (l & 15), a_col = (l >> 4) << 3;
    const int vb_row = (((l >> 3) & 1) << 3) + (l & 7);
    const int vb_col = (l >> 4) << 3;

    float4 acc[2][4];
#pragma unroll
    for (int m = 0; m < 2; m++)
#pragma unroll
        for (int j = 0; j < 4; j++) acc[m][j] = make_float4(0.f, 0.f, 0.f, 0.f);

    hgemm_issue(A, W, m0, n0, as_s, bs_s, 0, 0, tid);

    for (int ki = 0; ki < 8; ki++) {
        if (ki + 1 < 8) {
            hgemm_issue(A, W, m0, n0, as_s, bs_s, ki + 1, (ki + 1) & 1, tid);
            cpwait<1>();
        } else {
            cpwait<0>();
        }
        __syncthreads();

        const int buf = ki & 1;
        const uint32_t a0b = as_s + (uint32_t)((buf * 128 * 72 + (wm + a_row) * 72 + a_col) * 2);
        const uint32_t a1b = a0b + 16 * 72 * 2;
        const uint32_t wb = bs_s + (uint32_t)((buf * 64 * 72) * 2);

#pragma unroll
        for (int kc = 0; kc < 4; kc++) {
            uint32_t a0[4], a1[4];
            ldsm4(a0[0], a0[1], a0[2], a0[3], a0b + kc * 32);
            ldsm4(a1[0], a1[1], a1[2], a1[3], a1b + kc * 32);
#pragma unroll
            for (int j = 0; j < 2; j++) {
                uint32_t b0, b1, b2, b3;
                ldsm4t(b0, b1, b2, b3,
                       wb + (uint32_t)(((kc * 16 + vb_row) * 72 + wn + 16 * j + vb_col) * 2));
                mma_f16(acc[0][2 * j],     a0[0], a0[1], a0[2], a0[3], b0, b1);
                mma_f16(acc[1][2 * j],     a1[0], a1[1], a1[2], a1[3], b0, b1);
                mma_f16(acc[0][2 * j + 1], a0[0], a0[1], a0[2], a0[3], b2, b3);
                mma_f16(acc[1][2 * j + 1], a1[0], a1[1], a1[2], a1[3], b2, b3);
            }
        }
        __syncthreads();
    }

#pragma unroll
    for (int m = 0; m < 2; m++)
#pragma unroll
        for (int j = 0; j < 4; j++) {
            const int rg = m0 + wm + 16 * m + lr;
            const int cg = n0 + wn + 8 * j + 2 * lc;
            const float2 bv = *(const float2*)&bias[cg];
            if constexpr (sizeof(OutT) == 2) {
                *(__half2*)&C[(size_t)rg * 512 + cg] =
                    __floats2half2_rn(acc[m][j].x + bv.x, acc[m][j].y + bv.y);
                *(__half2*)&C[(size_t)(rg + 8) * 512 + cg] =
                    __floats2half2_rn(acc[m][j].z + bv.x, acc[m][j].w + bv.y);
            } else {
                *(float2*)&C[(size_t)rg * 512 + cg] =
                    make_float2(acc[m][j].x + bv.x, acc[m][j].y + bv.y);
                *(float2*)&C[(size_t)(rg + 8) * 512 + cg] =
                    make_float2(acc[m][j].z + bv.x, acc[m][j].w + bv.y);
            }
        }
}

// ---------------------------------------------------------------------------
// fp16 fused attention. CTA = (bh, 128 q rows); warp owns 16 q-rows x 64 kv.
// QK -> masked exp -> e to SMEM tile (+register repack) -> coalesced e store
// to gmem + PV from registers. ctx (fp16) scaled by 1/rowsum.
// smem halves: qs[128][72] + ks[2][64][72] + vs[2][64][72] + es[128][72]
//              (+ red 128 f32) = 74240 B
// ---------------------------------------------------------------------------
__global__ __launch_bounds__(256, 2)
void attn_fp16(float* __restrict__ dummy) {
    extern __shared__ __half smh[];
    __half* qs = smh;                  // [128][72]
    __half* ks = qs + 128 * 72;        // [2][64][72]
    __half* vs = ks + 2 * 64 * 72;     // [2][64][72]
    __half* es = vs + 2 * 64 * 72;     // [128][72] (64 cols used)
    float* red = (float*)(es + 128 * 72);   // [128]

    const int tid = threadIdx.x, l = tid & 31, w = tid >> 5;
    const int wq = w * 16;
    const int g = l >> 2, tig = l & 3;
    const int qt = blockIdx.x, bh = blockIdx.y, b = bh >> 3;
    const int q0 = qt * 128;

    const __half* qg = g_qh + ((size_t)bh * L_ + q0) * DH_;
    const __half* kg = g_kh + (size_t)bh * L_ * DH_;
    const __half* vg = g_vh + (size_t)bh * L_ * DH_;
    const uint8_t* mb = g_mask8 + (size_t)b * L_ * L_;

    const uint32_t qs_s = (uint32_t)__cvta_generic_to_shared(qs);
    const uint32_t ks_s = (uint32_t)__cvta_generic_to_shared(ks);
    const uint32_t vs_s = (uint32_t)__cvta_generic_to_shared(vs);

#define ISSUE_K(kt_, buf_)                                                     \
    do {                                                                       \
        _Pragma("unroll")                                                      \
        for (int t = 0; t < 2; t++) {                                          \
            const int s = tid + 256 * t;                                       \
            const int r = s >> 3, c = (s & 7) << 3;                            \
            cpa16(ks_s + (uint32_t)(((buf_) * 64 * 72 + r * 72 + c) * 2),      \
                  kg + (size_t)((kt_) * 64 + r) * DH_ + c);                    \
        }                                                                      \
        cpcommit();                                                            \
    } while (0)
#define ISSUE_V(kt_, buf_)                                                     \
    do {                                                                       \
        _Pragma("unroll")                                                      \
        for (int t = 0; t < 2; t++) {                                          \
            const int s = tid + 256 * t;                                       \
            const int r = s >> 3, c = (s & 7) << 3;                            \
            cpa16(vs_s + (uint32_t)(((buf_) * 64 * 72 + r * 72 + c) * 2),      \
                  vg + (size_t)((kt_) * 64 + r) * DH_ + c);                    \
        }                                                                      \
        cpcommit();                                                            \
    } while (0)

    // Q (group), K0 (group), V0 (group)
#pragma unroll
    for (int t = 0; t < 4; t++) {
        const int s = tid + 256 * t;
        const int r = s >> 3, c = (s & 7) << 3;
        cpa16(qs_s + (uint32_t)((r * 72 + c) * 2), qg + (size_t)r * DH_ + c);
    }
    cpcommit();
    ISSUE_K(0, 0);
    ISSUE_V(0, 0);

    // ldmatrix lane addressing
    const int a_row = wq + (l & 15);
    const int a_col = (l >> 4) << 3;
    const int kb_row = ((l >> 4) << 3) + (l & 7);
    const int kb_col = ((l >> 3) & 1) << 3;
    const int vb_row = (((l >> 3) & 1) << 3) + (l & 7);
    const int vb_col = (l >> 4) << 3;

    cpwait<2>();
    __syncthreads();

    uint32_t qa[4][4];
    const uint32_t qaddr = qs_s + (uint32_t)((a_row * 72 + a_col) * 2);
#pragma unroll
    for (int kc = 0; kc < 4; kc++)
        ldsm4(qa[kc][0], qa[kc][1], qa[kc][2], qa[kc][3], qaddr + kc * 32);

    float4 ctx[8];
#pragma unroll
    for (int j = 0; j < 8; j++) ctx[j] = make_float4(0.f, 0.f, 0.f, 0.f);
    float rs0 = 0.f, rs1 = 0.f;

    const int rg0 = q0 + wq + g;
    const int rg1 = rg0 + 8;
    const int er0 = wq + g;            // local e rows
    __half* eg = g_eh + ((size_t)bh * L_ + q0) * L_;

    for (int kt = 0; kt < 32; kt++) {
        const int buf = kt & 1;
        cpwait<1>();
        __syncthreads();

        // ---- QK^T ----
        float4 acc[8];
#pragma unroll
        for (int j = 0; j < 8; j++) acc[j] = make_float4(0.f, 0.f, 0.f, 0.f);

        const uint32_t ksb = ks_s + (uint32_t)(buf * 64 * 72 * 2);
#pragma unroll
        for (int kc = 0; kc < 4; kc++) {
#pragma unroll
            for (int q4 = 0; q4 < 4; q4++) {
                uint32_t b0, b1, b2, b3;
                ldsm4(b0, b1, b2, b3,
                      ksb + (uint32_t)(((q4 * 16 + kb_row) * 72 + kc * 16 + kb_col) * 2));
                mma_f16(acc[2 * q4],     qa[kc][0], qa[kc][1], qa[kc][2], qa[kc][3], b0, b1);
                mma_f16(acc[2 * q4 + 1], qa[kc][0], qa[kc][1], qa[kc][2], qa[kc][3], b2, b3);
            }
        }

        if (kt + 1 < 32) ISSUE_K(kt + 1, buf ^ 1);

        // ---- epilogue: masked exp -> es smem + register repack ----
        uint32_t plo[8], phi[8];
        const uint8_t* m0p = mb + (size_t)rg0 * L_ + kt * 64 + 2 * tig;
        const uint8_t* m1p = mb + (size_t)rg1 * L_ + kt * 64 + 2 * tig;
#pragma unroll
        for (int j = 0; j < 8; j++) {
            const int co = 8 * j;
            const uchar2 m0 = *(const uchar2*)(m0p + co);
            const uchar2 m1 = *(const uchar2*)(m1p + co);
            const float e0 = m0.x ? exp2f(acc[j].x * LOG2E_DIV32) : 0.f;
            const float e1 = m0.y ? exp2f(acc[j].y * LOG2E_DIV32) : 0.f;
            const float e2 = m1.x ? exp2f(acc[j].z * LOG2E_DIV32) : 0.f;
            const float e3 = m1.y ? exp2f(acc[j].w * LOG2E_DIV32) : 0.f;
            rs0 += e0 + e1;
            rs1 += e2 + e3;
            const __half2 h0 = __floats2half2_rn(e0, e1);
            const __half2 h1 = __floats2half2_rn(e2, e3);
            plo[j] = *(const uint32_t*)&h0;
            phi[j] = *(const uint32_t*)&h1;
            const int cl = co + 2 * tig;
            *(__half2*)&es[er0 * 72 + cl] = h0;
            *(__half2*)&es[(er0 + 8) * 72 + cl] = h1;
        }

        if (kt + 1 < 32) cpwait<1>(); else cpwait<0>();
        __syncthreads();   // publishes es + vs

        // ---- P @ V (A from registers) ----
        const uint32_t vsb = vs_s + (uint32_t)(buf * 64 * 72 * 2);
#pragma unroll
        for (int kc = 0; kc < 4; kc++) {
            const uint32_t a0 = plo[2 * kc], a1 = phi[2 * kc];
            const uint32_t a2 = plo[2 * kc + 1], a3 = phi[2 * kc + 1];
#pragma unroll
            for (int q4 = 0; q4 < 4; q4++) {
                uint32_t b0, b1, b2, b3;
                ldsm4t(b0, b1, b2, b3,
                       vsb + (uint32_t)(((kc * 16 + vb_row) * 72 + q4 * 16 + vb_col) * 2));
                mma_f16(ctx[2 * q4],     a0, a1, a2, a3, b0, b1);
                mma_f16(ctx[2 * q4 + 1], a0, a1, a2, a3, b2, b3);
            }
        }

        // ---- coalesced e tile store: 128 rows x 64 cols fp16 ----
#pragma unroll
        for (int t = 0; t < 4; t++) {
            const int s = tid + 256 * t;
            const int r = s >> 3, c = (s & 7) << 3;
            *(uint4*)(eg + (size_t)r * L_ + kt * 64 + c) = *(const uint4*)&es[r * 72 + c];
        }

        if (kt + 1 < 32) ISSUE_V(kt + 1, buf ^ 1);
    }

    // ---- rowsum reduce -> inv ----
    rs0 += __shfl_xor_sync(0xffffffffu, rs0, 1);
    rs0 += __shfl_xor_sync(0xffffffffu, rs0, 2);
    rs1 += __shfl_xor_sync(0xffffffffu, rs1, 1);
    rs1 += __shfl_xor_sync(0xffffffffu, rs1, 2);
    if (tig == 0) {
        red[wq + g] = rs0;
        red[wq + 8 + g] = rs1;
    }
    __syncthreads();
    if (tid < 128) {
        const float s = red[tid];
        const float iv = (s > 0.f) ? (1.f / s) : 0.f;
        g_inv[(size_t)bh * L_ + q0 + tid] = iv;
        red[tid] = iv;
    }
    __syncthreads();
    const float iv0 = red[wq + g];
    const float iv1 = red[wq + 8 + g];

    // ---- ctx write (normalized fp16) ----
#pragma unroll
    for (int j = 0; j < 8; j++) {
        const int cd = 8 * j + 2 * tig;
        *(__half2*)&g_ctxh[((size_t)bh * L_ + rg0) * DH_ + cd] =
            __floats2half2_rn(ctx[j].x * iv0, ctx[j].y * iv0);
        *(__half2*)&g_ctxh[((size_t)bh * L_ + rg1) * DH_ + cd] =
            __floats2half2_rn(ctx[j].z * iv1, ctx[j].w * iv1);
    }
    (void)dummy;
#undef ISSUE_K
#undef ISSUE_V
}

// ---------------------------------------------------------------------------
// rescale: attn[row][:] = fp32(g_eh[row][:]) * g_inv[row]
// ---------------------------------------------------------------------------
__global__ __launch_bounds__(256)
void rescale_attn(float* __restrict__ attn) {
    const int row = blockIdx.x;
    const float iv = g_inv[row];
    const uint4 u = reinterpret_cast<const uint4*>(g_eh + (size_t)row * L_)[threadIdx.x];
    float4 o0, o1;
    {
        const float2 f0 = __half22float2(*(const __half2*)&u.x);
        const float2 f1 = __half22float2(*(const __half2*)&u.y);
        o0 = make_float4(f0.x * iv, f0.y * iv, f1.x * iv, f1.y * iv);
    }
    {
        const float2 f0 = __half22float2(*(const __half2*)&u.z);
        const float2 f1 = __half22float2(*(const __half2*)&u.w);
        o1 = make_float4(f0.x * iv, f0.y * iv, f1.x * iv, f1.y * iv);
    }
    float4* dst = reinterpret_cast<float4*>(attn + (size_t)row * L_);
    dst[2 * threadIdx.x] = o0;
    dst[2 * threadIdx.x + 1] = o1;
}

// ---------------------------------------------------------------------------
extern "C" void kernel_launch(void* const* d_in, const int* in_sizes, int n_in,
                              void* d_out, int out_size) {
    const float* Q  = (const float*)d_in[0];
    const float* K  = (const float*)d_in[1];
    const float* V  = (const float*)d_in[2];
    const int*   Mk = (const int*)d_in[3];
    const float* Wq = (const float*)d_in[4];
    const float* bq = (const float*)d_in[5];
    const float* Wk = (const float*)d_in[6];
    const float* bk = (const float*)d_in[7];
    const float* Wv = (const float*)d_in[8];
    const float* bv = (const float*)d_in[9];
    const float* Wo = (const float*)d_in[10];
    const float* bo = (const float*)d_in[11];

    __half *qin, *kin, *vin, *wq, *wk, *wv, *wo, *qh, *kh, *vh, *ctxh;
    cudaGetSymbolAddress((void**)&qin, g_qin);
    cudaGetSymbolAddress((void**)&kin, g_kin);
    cudaGetSymbolAddress((void**)&vin, g_vin);
    cudaGetSymbolAddress((void**)&wq, g_wq);
    cudaGetSymbolAddress((void**)&wk, g_wk);
    cudaGetSymbolAddress((void**)&wv, g_wv);
    cudaGetSymbolAddress((void**)&wo, g_wo);
    cudaGetSymbolAddress((void**)&qh, g_qh);
    cudaGetSymbolAddress((void**)&kh, g_kh);
    cudaGetSymbolAddress((void**)&vh, g_vh);
    cudaGetSymbolAddress((void**)&ctxh, g_ctxh);

    float* out  = (float*)d_out;
    float* attn = out + OUT_ELEMS;   // concat(out, attn_dist)

    const int smem_gemm = (2 * 128 * 72 + 2 * 64 * 72) * 2;                  // 55296
    const int smem_attn = (128 * 72 + 4 * 64 * 72 + 128 * 72) * 2 + 128 * 4; // 74240
    cudaFuncSetAttribute(hgemm<__half>, cudaFuncAttributeMaxDynamicSharedMemorySize, smem_gemm);
    cudaFuncSetAttribute(hgemm<float>, cudaFuncAttributeMaxDynamicSharedMemorySize, smem_gemm);
    cudaFuncSetAttribute(attn_fp16, cudaFuncAttributeMaxDynamicSharedMemorySize, smem_attn);

    pack_mask<<<(B_ * L_ * L_) / 4 / 256, 256>>>(Mk);

    f2h<<<OUT_ELEMS / 4 / 256, 256>>>(Q, qin);
    f2h<<<OUT_ELEMS / 4 / 256, 256>>>(K, kin);
    f2h<<<OUT_ELEMS / 4 / 256, 256>>>(V, vin);
    f2h<<<(D_ * D_) / 4 / 256, 256>>>(Wq, wq);
    f2h<<<(D_ * D_) / 4 / 256, 256>>>(Wk, wk);
    f2h<<<(D_ * D_) / 4 / 256, 256>>>(Wv, wv);
    f2h<<<(D_ * D_) / 4 / 256, 256>>>(Wo, wo);

    const dim3 gg(8, 64);    // N/64, M/128
    hgemm<__half><<<gg, 256, smem_gemm>>>(qin, wq, bq, qh);
    hgemm<__half><<<gg, 256, smem_gemm>>>(kin, wk, bk, kh);
    hgemm<__half><<<gg, 256, smem_gemm>>>(vin, wv, bv, vh);

    const dim3 ga(16, 32);   // q-tiles of 128, b*h
    attn_fp16<<<ga, 256, smem_attn>>>(attn);

    rescale_attn<<<B_ * H_ * L_, 256>>>(attn);

    hgemm<float><<<gg, 256, smem_gemm>>>(ctxh, wo, bo, out);
}